// round 7
// baseline (speedup 1.0000x reference)
#include <cuda_runtime.h>
#include <cuda_bf16.h>
#include <cstdint>

using bf16  = __nv_bfloat16;
using bf162 = __nv_bfloat162;

static constexpr int Bb = 32, Cc = 512, Nn = 1024, C3 = 1536;

// ---------------- device scratch ----------------
__device__ __align__(16) float g_ga[Bb * Cc];
__device__ __align__(16) float g_gb[Bb * Cc];
__device__ __align__(16) bf16  g_w1b[C3 * Cc];
__device__ __align__(16) bf16  g_w2b[Cc * Cc];
__device__ __align__(16) bf16  g_xnT [(size_t)Bb * Nn * Cc];
__device__ __align__(16) bf16  g_qkv [(size_t)Bb * C3 * Nn];
__device__ __align__(16) bf16  g_qt  [(size_t)Bb * Nn * Cc];
__device__ __align__(16) bf16  g_kt  [(size_t)Bb * Nn * Cc];
__device__ __align__(16) float g_S   [(size_t)Bb * Nn * Nn];
__device__ __align__(16) bf16  g_P   [(size_t)Bb * Nn * Nn];
__device__ __align__(16) bf16  g_attn[(size_t)Bb * Nn * Cc];

// ---------------- PTX helpers ----------------
__device__ __forceinline__ uint32_t smem_u32(const void* p) {
    return (uint32_t)__cvta_generic_to_shared(p);
}
__device__ __forceinline__ void cp_async16(uint32_t s, const void* g) {
    asm volatile("cp.async.cg.shared.global [%0], [%1], 16;\n" :: "r"(s), "l"(g));
}
__device__ __forceinline__ void cp_commit() {
    asm volatile("cp.async.commit_group;\n" ::: "memory");
}
template <int N>
__device__ __forceinline__ void cp_wait() {
    asm volatile("cp.async.wait_group %0;\n" :: "n"(N) : "memory");
}
__device__ __forceinline__ void ldsm_x4(uint32_t* r, uint32_t addr) {
    asm volatile("ldmatrix.sync.aligned.m8n8.x4.shared.b16 {%0,%1,%2,%3}, [%4];\n"
                 : "=r"(r[0]), "=r"(r[1]), "=r"(r[2]), "=r"(r[3]) : "r"(addr));
}
__device__ __forceinline__ void mma_16816(float* d, const uint32_t* a,
                                          uint32_t b0, uint32_t b1) {
    asm volatile("mma.sync.aligned.m16n8k16.row.col.f32.bf16.bf16.f32 "
                 "{%0,%1,%2,%3}, {%4,%5,%6,%7}, {%8,%9}, {%0,%1,%2,%3};\n"
                 : "+f"(d[0]), "+f"(d[1]), "+f"(d[2]), "+f"(d[3])
                 : "r"(a[0]), "r"(a[1]), "r"(a[2]), "r"(a[3]), "r"(b0), "r"(b1));
}

// ---------------- mma.sync GEMM: D[M,N] = A[M,K] @ B[N,K]^T ----------------
// 128x128 tile, 128 threads, 2x2 warps, warp tile 64x64, BK=64, 2 stages.
// EPI: 0 = bf16 + bias[row], 1 = f32, 2 = bf16, 3 = f32 + bias[row] + resid
static constexpr int BM = 128, BN = 128, BK = 64, PAD = 8, NST = 2;
static constexpr int LDT = BK + PAD;                 // 72 halves per row
static constexpr int SAe = BM * LDT;                 // elems per stage per operand
static constexpr int GSMEM = 2 * NST * SAe * 2;      // 73728 bytes

template <int EPI>
__global__ __launch_bounds__(128) void gemm_bt(
        const bf16* __restrict__ A, const bf16* __restrict__ B, void* __restrict__ C,
        const float* __restrict__ bias, const float* __restrict__ resid,
        int M, int N, int K, int ldA, int ldB, int ldC,
        long sA, long sB, long sC, long sR) {
    extern __shared__ bf16 sm[];
    bf16* AsAll = sm;
    bf16* BsAll = sm + NST * SAe;

    const int tid = threadIdx.x, lane = tid & 31, wid = tid >> 5;
    const int wm = wid & 1, wn = wid >> 1;  // 2x2 warps, warp tile 64x64
    const int m0 = blockIdx.y * BM, n0 = blockIdx.x * BN, bz = blockIdx.z;
    A += (size_t)bz * sA;
    B += (size_t)bz * sB;

    float acc[4][8][4];
    #pragma unroll
    for (int i = 0; i < 4; ++i)
        #pragma unroll
        for (int j = 0; j < 8; ++j)
            #pragma unroll
            for (int k = 0; k < 4; ++k) acc[i][j][k] = 0.f;

    const int lr = tid >> 3, lc = (tid & 7) * 8;  // 16B chunks: 16 rows x 8 chunks/row

    auto load_stage = [&](int kt, int s) {
        bf16* As = AsAll + s * SAe;
        bf16* Bs = BsAll + s * SAe;
        const bf16* Ag = A + (size_t)m0 * ldA + kt * BK;
        const bf16* Bg = B + (size_t)n0 * ldB + kt * BK;
        #pragma unroll
        for (int i = 0; i < 8; ++i) {
            int r = lr + i * 16;
            cp_async16(smem_u32(As + r * LDT + lc), Ag + (size_t)r * ldA + lc);
        }
        #pragma unroll
        for (int i = 0; i < 8; ++i) {
            int r = lr + i * 16;
            cp_async16(smem_u32(Bs + r * LDT + lc), Bg + (size_t)r * ldB + lc);
        }
        cp_commit();
    };

    const int KT = K / BK;
    load_stage(0, 0);

    for (int kt = 0; kt < KT; ++kt) {
        if (kt + 1 < KT) {
            load_stage(kt + 1, (kt + 1) & 1);
            cp_wait<1>();
        } else {
            cp_wait<0>();
        }
        __syncthreads();

        const bf16* As = AsAll + (kt & 1) * SAe;
        const bf16* Bs = BsAll + (kt & 1) * SAe;
        uint32_t aAddr = smem_u32(As + (wm * 64 + (lane & 15)) * LDT + (lane >> 4) * 8);
        uint32_t bAddr = smem_u32(Bs + (wn * 64 + (lane & 15)) * LDT + (lane >> 4) * 8);

        #pragma unroll
        for (int ks = 0; ks < 4; ++ks) {
            uint32_t ar[4][4], br[4][4];
            #pragma unroll
            for (int mt = 0; mt < 4; ++mt)
                ldsm_x4(ar[mt], aAddr + (uint32_t)(mt * 16 * LDT + ks * 16) * 2);
            #pragma unroll
            for (int j = 0; j < 4; ++j)
                ldsm_x4(br[j], bAddr + (uint32_t)(j * 16 * LDT + ks * 16) * 2);
            #pragma unroll
            for (int mt = 0; mt < 4; ++mt)
                #pragma unroll
                for (int nn = 0; nn < 8; ++nn)
                    mma_16816(acc[mt][nn], ar[mt],
                              br[nn >> 1][nn & 1], br[nn >> 1][(nn & 1) + 2]);
        }
        __syncthreads();
    }

    // epilogue: warp covers rows [wm*64, +64), cols [wn*64, +64)
    const int g = lane >> 2, tc = lane & 3;
    #pragma unroll
    for (int mt = 0; mt < 4; ++mt) {
        int row = m0 + wm * 64 + mt * 16 + g;
        float bv0 = 0.f, bv1 = 0.f;
        if constexpr (EPI == 0 || EPI == 3) { bv0 = bias[row]; bv1 = bias[row + 8]; }
        #pragma unroll
        for (int nn = 0; nn < 8; ++nn) {
            int col = n0 + wn * 64 + nn * 8 + tc * 2;
            float* a4 = acc[mt][nn];
            if constexpr (EPI == 1 || EPI == 3) {
                float* Cp = (float*)C + (size_t)bz * sC;
                float2 v0 = make_float2(a4[0], a4[1]);
                float2 v1 = make_float2(a4[2], a4[3]);
                if constexpr (EPI == 3) {
                    const float* Rp = resid + (size_t)bz * sR;
                    float2 x0 = *(const float2*)&Rp[(size_t)row * ldC + col];
                    float2 x1 = *(const float2*)&Rp[(size_t)(row + 8) * ldC + col];
                    v0.x += bv0 + x0.x; v0.y += bv0 + x0.y;
                    v1.x += bv1 + x1.x; v1.y += bv1 + x1.y;
                }
                *(float2*)&Cp[(size_t)row * ldC + col]       = v0;
                *(float2*)&Cp[(size_t)(row + 8) * ldC + col] = v1;
            } else {
                bf16* Cp = (bf16*)C + (size_t)bz * sC;
                *(bf162*)&Cp[(size_t)row * ldC + col] =
                    __floats2bfloat162_rn(a4[0] + bv0, a4[1] + bv0);
                *(bf162*)&Cp[(size_t)(row + 8) * ldC + col] =
                    __floats2bfloat162_rn(a4[2] + bv1, a4[3] + bv1);
            }
        }
    }
}

// ---------------- stage 1: weight convert ----------------
__global__ void wconv_kernel(const float* __restrict__ w1, const float* __restrict__ w2,
                             bf16* __restrict__ w1b, bf16* __restrict__ w2b) {
    int i = blockIdx.x * 256 + threadIdx.x;
    if (i < C3 * Cc) w1b[i] = __float2bfloat16(w1[i]);
    if (i < Cc * Cc) w2b[i] = __float2bfloat16(w2[i]);
}

// ---------------- stage 2: groupnorm stats ----------------
__global__ __launch_bounds__(256) void gn_stats_kernel(
        const float* __restrict__ x, const float* __restrict__ gns,
        const float* __restrict__ gnb, float* __restrict__ ga, float* __restrict__ gb) {
    int bg = blockIdx.x;
    const float4* p = reinterpret_cast<const float4*>(x) + (size_t)bg * 4096;
    float s = 0.f, ss = 0.f;
    for (int i = threadIdx.x; i < 4096; i += 256) {
        float4 v = p[i];
        s  += v.x + v.y + v.z + v.w;
        ss += v.x * v.x + v.y * v.y + v.z * v.z + v.w * v.w;
    }
    __shared__ float sh[34];
    #pragma unroll
    for (int o = 16; o > 0; o >>= 1) {
        s  += __shfl_xor_sync(~0u, s, o);
        ss += __shfl_xor_sync(~0u, ss, o);
    }
    int w = threadIdx.x >> 5;
    if ((threadIdx.x & 31) == 0) { sh[w] = s; sh[w + 8] = ss; }
    __syncthreads();
    if (threadIdx.x == 0) {
        float ts = 0.f, tss = 0.f;
        #pragma unroll
        for (int i = 0; i < 8; ++i) { ts += sh[i]; tss += sh[i + 8]; }
        sh[32] = ts; sh[33] = tss;
    }
    __syncthreads();
    float mean = sh[32] * (1.f / 16384.f);
    float var  = sh[33] * (1.f / 16384.f) - mean * mean;
    float rstd = rsqrtf(var + 1e-5f);
    if (threadIdx.x < 16) {
        int b = bg >> 5, gI = bg & 31, c = gI * 16 + threadIdx.x;
        float sc = gns[c] * rstd;
        ga[b * Cc + c] = sc;
        gb[b * Cc + c] = gnb[c] - mean * sc;
    }
}

// ---------------- stage 3: normalize + transpose -> xnT[b][n][c] ----------------
__global__ void gn_apply_t_kernel(const float* __restrict__ x, const float* __restrict__ ga,
                                  const float* __restrict__ gb, bf16* __restrict__ xnT) {
    __shared__ float t[32][33];
    int b = blockIdx.z;
    const float* xb = x + (size_t)b * Cc * Nn;
    int n0 = blockIdx.x * 32, c0 = blockIdx.y * 32;
    #pragma unroll
    for (int j = 0; j < 4; ++j) {
        int c = c0 + threadIdx.y + 8 * j;
        float v = xb[(size_t)c * Nn + n0 + threadIdx.x];
        t[threadIdx.y + 8 * j][threadIdx.x] = v * ga[b * Cc + c] + gb[b * Cc + c];
    }
    __syncthreads();
    bf16* ob = xnT + (size_t)b * Nn * Cc;
    #pragma unroll
    for (int j = 0; j < 4; ++j) {
        int n = n0 + threadIdx.y + 8 * j;
        ob[(size_t)n * Cc + c0 + threadIdx.x] =
            __float2bfloat16(t[threadIdx.x][threadIdx.y + 8 * j]);
    }
}

// ---------------- stage 5: transpose q,k: qkv[o,n] -> qt/kt[n,c] ----------------
__global__ void transpose_qk_kernel(const bf16* __restrict__ qkv,
                                    bf16* __restrict__ qt, bf16* __restrict__ kt) {
    __shared__ bf16 t[32][33];
    int z = blockIdx.z, b = z >> 1, sel = z & 1;
    const bf16* src = qkv + (size_t)b * C3 * Nn + (size_t)sel * Cc * Nn;
    bf16* dst = (sel ? kt : qt) + (size_t)b * Nn * Cc;
    int n = blockIdx.x * 32 + threadIdx.x;
    int c0 = blockIdx.y * 32;
    #pragma unroll
    for (int j = 0; j < 4; ++j)
        t[threadIdx.y + 8 * j][threadIdx.x] = src[(size_t)(c0 + threadIdx.y + 8 * j) * Nn + n];
    __syncthreads();
    int nn = blockIdx.x * 32 + threadIdx.y;
    int cc = c0 + threadIdx.x;
    #pragma unroll
    for (int j = 0; j < 4; ++j)
        dst[(size_t)(nn + 8 * j) * Cc + cc] = t[threadIdx.x][threadIdx.y + 8 * j];
}

// ---------------- stage 7: softmax rows fp32 -> bf16 ----------------
__global__ __launch_bounds__(256) void softmax_kernel(const float* __restrict__ S,
                                                      bf16* __restrict__ P) {
    size_t r = blockIdx.x;
    float4 v = reinterpret_cast<const float4*>(S + r * Nn)[threadIdx.x];
    const float sc = 0.04419417382415922f;  // 512^-0.5
    v.x *= sc; v.y *= sc; v.z *= sc; v.w *= sc;
    __shared__ float sh[8];
    __shared__ float bmax, bsum;
    float m = fmaxf(fmaxf(v.x, v.y), fmaxf(v.z, v.w));
    #pragma unroll
    for (int o = 16; o > 0; o >>= 1) m = fmaxf(m, __shfl_xor_sync(~0u, m, o));
    if ((threadIdx.x & 31) == 0) sh[threadIdx.x >> 5] = m;
    __syncthreads();
    if (threadIdx.x == 0) {
        float mm = sh[0];
        #pragma unroll
        for (int i = 1; i < 8; ++i) mm = fmaxf(mm, sh[i]);
        bmax = mm;
    }
    __syncthreads();
    m = bmax;
    float4 e;
    e.x = __expf(v.x - m); e.y = __expf(v.y - m);
    e.z = __expf(v.z - m); e.w = __expf(v.w - m);
    float s = e.x + e.y + e.z + e.w;
    #pragma unroll
    for (int o = 16; o > 0; o >>= 1) s += __shfl_xor_sync(~0u, s, o);
    if ((threadIdx.x & 31) == 0) sh[threadIdx.x >> 5] = s;
    __syncthreads();
    if (threadIdx.x == 0) {
        float t = 0.f;
        #pragma unroll
        for (int i = 0; i < 8; ++i) t += sh[i];
        bsum = t;
    }
    __syncthreads();
    float inv = 1.f / bsum;
    bf162* o2 = reinterpret_cast<bf162*>(P + r * Nn) + threadIdx.x * 2;
    o2[0] = __floats2bfloat162_rn(e.x * inv, e.y * inv);
    o2[1] = __floats2bfloat162_rn(e.z * inv, e.w * inv);
}

// ---------------- host launcher ----------------
extern "C" void kernel_launch(void* const* d_in, const int* in_sizes, int n_in,
                              void* d_out, int out_size) {
    (void)in_sizes; (void)n_in; (void)out_size;
    const float* x   = (const float*)d_in[0];
    const float* gns = (const float*)d_in[1];
    const float* gnb = (const float*)d_in[2];
    const float* w1  = (const float*)d_in[3];
    const float* b1  = (const float*)d_in[4];
    const float* w2  = (const float*)d_in[5];
    const float* b2  = (const float*)d_in[6];
    float* out = (float*)d_out;

    void *pga, *pgb, *pw1, *pw2, *pxn, *pqkv, *pqt, *pkt, *pS, *pP, *pattn;
    cudaGetSymbolAddress(&pga, g_ga);
    cudaGetSymbolAddress(&pgb, g_gb);
    cudaGetSymbolAddress(&pw1, g_w1b);
    cudaGetSymbolAddress(&pw2, g_w2b);
    cudaGetSymbolAddress(&pxn, g_xnT);
    cudaGetSymbolAddress(&pqkv, g_qkv);
    cudaGetSymbolAddress(&pqt, g_qt);
    cudaGetSymbolAddress(&pkt, g_kt);
    cudaGetSymbolAddress(&pS, g_S);
    cudaGetSymbolAddress(&pP, g_P);
    cudaGetSymbolAddress(&pattn, g_attn);

    cudaFuncSetAttribute(gemm_bt<0>, cudaFuncAttributeMaxDynamicSharedMemorySize, GSMEM);
    cudaFuncSetAttribute(gemm_bt<1>, cudaFuncAttributeMaxDynamicSharedMemorySize, GSMEM);
    cudaFuncSetAttribute(gemm_bt<2>, cudaFuncAttributeMaxDynamicSharedMemorySize, GSMEM);
    cudaFuncSetAttribute(gemm_bt<3>, cudaFuncAttributeMaxDynamicSharedMemorySize, GSMEM);

    // 1) weights -> bf16
    wconv_kernel<<<3072, 256>>>(w1, w2, (bf16*)pw1, (bf16*)pw2);
    // 2) groupnorm stats
    gn_stats_kernel<<<Bb * 32, 256>>>(x, gns, gnb, (float*)pga, (float*)pgb);
    // 3) normalize + transpose -> xnT [b,n,c]
    gn_apply_t_kernel<<<dim3(32, 16, Bb), dim3(32, 8)>>>(x, (float*)pga, (float*)pgb,
                                                         (bf16*)pxn);
    // 4) QKV: qkv[o,n] = w1[o,:] . xnT[n,:] + b1[o]
    gemm_bt<0><<<dim3(8, 12, Bb), 128, GSMEM>>>(
        (const bf16*)pw1, (const bf16*)pxn, pqkv, b1, nullptr,
        C3, Nn, Cc, Cc, Cc, Nn, 0L, (long)Nn * Cc, (long)C3 * Nn, 0L);
    // 5) transpose q,k -> [n,c]
    transpose_qk_kernel<<<dim3(32, 16, 2 * Bb), dim3(32, 8)>>>((const bf16*)pqkv,
                                                               (bf16*)pqt, (bf16*)pkt);
    // 6) S[n,m] = qt[n,:] . kt[m,:]  (fp32)
    gemm_bt<1><<<dim3(8, 8, Bb), 128, GSMEM>>>(
        (const bf16*)pqt, (const bf16*)pkt, pS, nullptr, nullptr,
        Nn, Nn, Cc, Cc, Cc, Nn, (long)Nn * Cc, (long)Nn * Cc, (long)Nn * Nn, 0L);
    // 7) softmax -> P bf16
    softmax_kernel<<<Bb * Nn, 256>>>((const float*)pS, (bf16*)pP);
    // 8) attn[n,c] = P[n,:] . v[c,:]   (v rows of qkv, [c,m] K-major)
    gemm_bt<2><<<dim3(4, 8, Bb), 128, GSMEM>>>(
        (const bf16*)pP, (const bf16*)pqkv + (size_t)2 * Cc * Nn, pattn, nullptr, nullptr,
        Nn, Cc, Nn, Nn, Nn, Cc, (long)Nn * Nn, (long)C3 * Nn, (long)Nn * Cc, 0L);
    // 9) out[o,n] = w2[o,:] . attn[n,:] + b2[o] + x[o,n]  (fused residual)
    gemm_bt<3><<<dim3(8, 4, Bb), 128, GSMEM>>>(
        (const bf16*)pw2, (const bf16*)pattn, out, b2, x,
        Cc, Nn, Cc, Cc, Cc, Nn, 0L, (long)Nn * Cc, (long)Cc * Nn, (long)Cc * Nn);
}

// round 8
// speedup vs baseline: 1.0671x; 1.0671x over previous
#include <cuda_runtime.h>
#include <cuda_bf16.h>
#include <cstdint>

using bf16  = __nv_bfloat16;
using bf162 = __nv_bfloat162;

static constexpr int Bb = 32, Cc = 512, Nn = 1024, C3 = 1536;

// ---------------- device scratch ----------------
__device__ __align__(16) float g_ga[Bb * Cc];
__device__ __align__(16) float g_gb[Bb * Cc];
__device__ __align__(16) bf16  g_w1b[C3 * Cc];
__device__ __align__(16) bf16  g_w2b[Cc * Cc];
__device__ __align__(16) bf16  g_xnT [(size_t)Bb * Nn * Cc];
__device__ __align__(16) bf16  g_qkv [(size_t)Bb * C3 * Nn];
__device__ __align__(16) bf16  g_P   [(size_t)Bb * Nn * Nn];
__device__ __align__(16) bf16  g_attn[(size_t)Bb * Nn * Cc];

// ---------------- PTX helpers ----------------
__device__ __forceinline__ uint32_t smem_u32(const void* p) {
    return (uint32_t)__cvta_generic_to_shared(p);
}
__device__ __forceinline__ void cp_async16(uint32_t s, const void* g) {
    asm volatile("cp.async.cg.shared.global [%0], [%1], 16;\n" :: "r"(s), "l"(g));
}
__device__ __forceinline__ void cp_commit() {
    asm volatile("cp.async.commit_group;\n" ::: "memory");
}
template <int N>
__device__ __forceinline__ void cp_wait() {
    asm volatile("cp.async.wait_group %0;\n" :: "n"(N) : "memory");
}
__device__ __forceinline__ void ldsm_x4(uint32_t* r, uint32_t addr) {
    asm volatile("ldmatrix.sync.aligned.m8n8.x4.shared.b16 {%0,%1,%2,%3}, [%4];\n"
                 : "=r"(r[0]), "=r"(r[1]), "=r"(r[2]), "=r"(r[3]) : "r"(addr));
}
__device__ __forceinline__ void ldsm_x4_t(uint32_t* r, uint32_t addr) {
    asm volatile("ldmatrix.sync.aligned.m8n8.x4.trans.shared.b16 {%0,%1,%2,%3}, [%4];\n"
                 : "=r"(r[0]), "=r"(r[1]), "=r"(r[2]), "=r"(r[3]) : "r"(addr));
}
__device__ __forceinline__ void mma_16816(float* d, const uint32_t* a,
                                          uint32_t b0, uint32_t b1) {
    asm volatile("mma.sync.aligned.m16n8k16.row.col.f32.bf16.bf16.f32 "
                 "{%0,%1,%2,%3}, {%4,%5,%6,%7}, {%8,%9}, {%0,%1,%2,%3};\n"
                 : "+f"(d[0]), "+f"(d[1]), "+f"(d[2]), "+f"(d[3])
                 : "r"(a[0]), "r"(a[1]), "r"(a[2]), "r"(a[3]), "r"(b0), "r"(b1));
}

// ---------------- mma.sync GEMM: D[M,N] = A[M,K] @ B[N,K]^T (R4 config) -------
// 128x128 tile, 256 threads, 2x4 warps (warp 64x32), BK=64, 3 stages.
// EPI: 0 = bf16 + bias[row], 1 = f32, 2 = bf16, 3 = f32 + bias[row] + resid
static constexpr int BM = 128, BN = 128, BK = 64, PAD = 8, NST = 3;
static constexpr int LDT = BK + PAD;
static constexpr int SAe = BM * LDT;
static constexpr int GSMEM = 2 * NST * SAe * 2;

template <int EPI>
__global__ __launch_bounds__(256) void gemm_bt(
        const bf16* __restrict__ A, const bf16* __restrict__ B, void* __restrict__ C,
        const float* __restrict__ bias, const float* __restrict__ resid,
        int M, int N, int K, int ldA, int ldB, int ldC,
        long sA, long sB, long sC, long sR) {
    extern __shared__ bf16 sm[];
    bf16* AsAll = sm;
    bf16* BsAll = sm + NST * SAe;

    const int tid = threadIdx.x, lane = tid & 31, wid = tid >> 5;
    const int wm = wid & 1, wn = wid >> 1;
    const int m0 = blockIdx.y * BM, n0 = blockIdx.x * BN, bz = blockIdx.z;
    A += (size_t)bz * sA;
    B += (size_t)bz * sB;

    float acc[4][4][4];
    #pragma unroll
    for (int i = 0; i < 4; ++i)
        #pragma unroll
        for (int j = 0; j < 4; ++j)
            #pragma unroll
            for (int k = 0; k < 4; ++k) acc[i][j][k] = 0.f;

    const int lr = tid >> 3, lc = (tid & 7) * 8;

    auto load_stage = [&](int kt, int s) {
        bf16* As = AsAll + s * SAe;
        bf16* Bs = BsAll + s * SAe;
        const bf16* Ag = A + (size_t)m0 * ldA + kt * BK;
        const bf16* Bg = B + (size_t)n0 * ldB + kt * BK;
        #pragma unroll
        for (int i = 0; i < 4; ++i) {
            int r = lr + i * 32;
            cp_async16(smem_u32(As + r * LDT + lc), Ag + (size_t)r * ldA + lc);
        }
        #pragma unroll
        for (int i = 0; i < 4; ++i) {
            int r = lr + i * 32;
            cp_async16(smem_u32(Bs + r * LDT + lc), Bg + (size_t)r * ldB + lc);
        }
        cp_commit();
    };

    const int KT = K / BK;
    load_stage(0, 0);
    load_stage(1, 1);

    int sIdx = 0;
    for (int kt = 0; kt < KT; ++kt) {
        if (kt == KT - 1) cp_wait<0>(); else cp_wait<1>();
        __syncthreads();
        if (kt + 2 < KT) {
            int ns = sIdx + 2; if (ns >= NST) ns -= NST;
            load_stage(kt + 2, ns);
        }

        const bf16* As = AsAll + sIdx * SAe;
        const bf16* Bs = BsAll + sIdx * SAe;
        uint32_t aAddr = smem_u32(As + (wm * 64 + (lane & 15)) * LDT + (lane >> 4) * 8);
        uint32_t bAddr = smem_u32(Bs + (wn * 32 + (lane & 15)) * LDT + (lane >> 4) * 8);

        #pragma unroll
        for (int ks = 0; ks < 4; ++ks) {
            uint32_t ar[4][4], br[2][4];
            #pragma unroll
            for (int mt = 0; mt < 4; ++mt)
                ldsm_x4(ar[mt], aAddr + (uint32_t)(mt * 16 * LDT + ks * 16) * 2);
            #pragma unroll
            for (int rg = 0; rg < 2; ++rg)
                ldsm_x4(br[rg], bAddr + (uint32_t)(rg * 16 * LDT + ks * 16) * 2);
            #pragma unroll
            for (int mt = 0; mt < 4; ++mt)
                #pragma unroll
                for (int nt = 0; nt < 4; ++nt)
                    mma_16816(acc[mt][nt], ar[mt],
                              br[nt >> 1][nt & 1], br[nt >> 1][(nt & 1) + 2]);
        }
        ++sIdx; if (sIdx >= NST) sIdx = 0;
    }

    const int g = lane >> 2, tc = lane & 3;
    #pragma unroll
    for (int mt = 0; mt < 4; ++mt) {
        int row = m0 + wm * 64 + mt * 16 + g;
        float bv0 = 0.f, bv1 = 0.f;
        if constexpr (EPI == 0 || EPI == 3) { bv0 = bias[row]; bv1 = bias[row + 8]; }
        #pragma unroll
        for (int nt = 0; nt < 4; ++nt) {
            int col = n0 + wn * 32 + nt * 8 + tc * 2;
            float* a4 = acc[mt][nt];
            if constexpr (EPI == 1 || EPI == 3) {
                float* Cp = (float*)C + (size_t)bz * sC;
                float2 v0 = make_float2(a4[0], a4[1]);
                float2 v1 = make_float2(a4[2], a4[3]);
                if constexpr (EPI == 3) {
                    const float* Rp = resid + (size_t)bz * sR;
                    float2 x0 = *(const float2*)&Rp[(size_t)row * ldC + col];
                    float2 x1 = *(const float2*)&Rp[(size_t)(row + 8) * ldC + col];
                    v0.x += bv0 + x0.x; v0.y += bv0 + x0.y;
                    v1.x += bv1 + x1.x; v1.y += bv1 + x1.y;
                }
                *(float2*)&Cp[(size_t)row * ldC + col]       = v0;
                *(float2*)&Cp[(size_t)(row + 8) * ldC + col] = v1;
            } else {
                bf16* Cp = (bf16*)C + (size_t)bz * sC;
                *(bf162*)&Cp[(size_t)row * ldC + col] =
                    __floats2bfloat162_rn(a4[0] + bv0, a4[1] + bv0);
                *(bf162*)&Cp[(size_t)(row + 8) * ldC + col] =
                    __floats2bfloat162_rn(a4[2] + bv1, a4[3] + bv1);
            }
        }
    }
}

// ---------------- fused S + softmax: P[32 x 1024] per CTA -------------------
// S[n,m] = sum_c q[c,n] k[c,m]; reads q,k straight from qkv [c][n] layout via
// ldmatrix.trans. Full N=1024 per CTA -> row softmax is CTA-local.
// 256 thr, 8 warps = 2(M) x 4(N); warp tile 16 x 256; acc 128 f32/thread.
static constexpr int SB_M = 32, SB_K = 32;
static constexpr int S_LDA = 40;                    // halves
static constexpr int S_LDB = 1032;                  // 1024 + 8 pad
static constexpr int S_ASZ = SB_K * S_LDA;          // 1280
static constexpr int S_BSZ = SB_K * S_LDB;          // 33024
static constexpr int S_SMEM = 2 * (S_ASZ + S_BSZ) * 2;  // 137216 B

__global__ __launch_bounds__(256) void s_softmax_kernel(
        const bf16* __restrict__ qkv, bf16* __restrict__ P) {
    extern __shared__ bf16 ssm[];
    bf16* As = ssm;                 // 2 stages of [SB_K][S_LDA]
    bf16* Bs = ssm + 2 * S_ASZ;     // 2 stages of [SB_K][S_LDB]
    __shared__ float ssum[2][16][4];

    const int tid = threadIdx.x, lane = tid & 31, wid = tid >> 5;
    const int wm = wid & 1, wn = wid >> 1;          // 2 x 4
    const int nblk = blockIdx.x, b = blockIdx.y;
    const bf16* qg = qkv + (size_t)b * C3 * Nn;     // [c][n]
    const bf16* kg = qg + (size_t)Cc * Nn;          // [c][m]

    float acc[32][4];
    #pragma unroll
    for (int j = 0; j < 32; ++j)
        #pragma unroll
        for (int t = 0; t < 4; ++t) acc[j][t] = 0.f;

    auto load_stage = [&](int kt, int s) {
        if (tid < 128) {
            int r = tid >> 2, cchunk = tid & 3;
            cp_async16(smem_u32(As + s * S_ASZ + r * S_LDA + cchunk * 8),
                       qg + (size_t)(kt * SB_K + r) * Nn + nblk * SB_M + cchunk * 8);
        }
        #pragma unroll
        for (int i = 0; i < 16; ++i) {
            int ch = i * 256 + tid;
            int r = ch >> 7, cchunk = ch & 127;
            cp_async16(smem_u32(Bs + s * S_BSZ + r * S_LDB + cchunk * 8),
                       kg + (size_t)(kt * SB_K + r) * Nn + cchunk * 8);
        }
        cp_commit();
    };

    const int KT = Cc / SB_K;  // 16
    load_stage(0, 0);

    // trans-ldsm lane maps:
    //  A (from [c][n]): c = (lane&7)+((lane&16)>>1), n_off = ((lane>>3)&1)*8
    //  B (from [c][m]): c = lane&15,                m_off = (lane>>4)*8
    const int aRow = (lane & 7) + ((lane & 16) >> 1);
    const int aCol = wm * 16 + ((lane >> 3) & 1) * 8;
    const int bRow = lane & 15;
    const int bCol = wn * 256 + (lane >> 4) * 8;

    for (int kt = 0; kt < KT; ++kt) {
        if (kt + 1 < KT) {
            load_stage(kt + 1, (kt + 1) & 1);
            cp_wait<1>();
        } else {
            cp_wait<0>();
        }
        __syncthreads();

        uint32_t aBase = smem_u32(As + (kt & 1) * S_ASZ + aRow * S_LDA + aCol);
        uint32_t bBase = smem_u32(Bs + (kt & 1) * S_BSZ + bRow * S_LDB + bCol);

        #pragma unroll
        for (int ks = 0; ks < 2; ++ks) {
            uint32_t ar[4];
            ldsm_x4_t(ar, aBase + (uint32_t)(ks * 16 * S_LDA) * 2);
            #pragma unroll
            for (int j = 0; j < 16; ++j) {
                uint32_t br[4];
                ldsm_x4_t(br, bBase + (uint32_t)(ks * 16 * S_LDB + j * 16) * 2);
                mma_16816(acc[j * 2],     ar, br[0], br[1]);
                mma_16816(acc[j * 2 + 1], ar, br[2], br[3]);
            }
        }
        __syncthreads();
    }

    // epilogue: exp, CTA-wide row sums, normalize, bf16 store
    const float scl = 0.04419417382415922f;  // 512^-0.5
    float rs_lo = 0.f, rs_hi = 0.f;
    #pragma unroll
    for (int j = 0; j < 32; ++j) {
        acc[j][0] = __expf(acc[j][0] * scl);
        acc[j][1] = __expf(acc[j][1] * scl);
        acc[j][2] = __expf(acc[j][2] * scl);
        acc[j][3] = __expf(acc[j][3] * scl);
        rs_lo += acc[j][0] + acc[j][1];
        rs_hi += acc[j][2] + acc[j][3];
    }
    rs_lo += __shfl_xor_sync(~0u, rs_lo, 1);
    rs_lo += __shfl_xor_sync(~0u, rs_lo, 2);
    rs_hi += __shfl_xor_sync(~0u, rs_hi, 1);
    rs_hi += __shfl_xor_sync(~0u, rs_hi, 2);
    const int g = lane >> 2, tc = lane & 3;
    if (tc == 0) {
        ssum[wm][g][wn]     = rs_lo;
        ssum[wm][g + 8][wn] = rs_hi;
    }
    __syncthreads();
    float inv_lo = 1.f / (ssum[wm][g][0] + ssum[wm][g][1] +
                          ssum[wm][g][2] + ssum[wm][g][3]);
    float inv_hi = 1.f / (ssum[wm][g + 8][0] + ssum[wm][g + 8][1] +
                          ssum[wm][g + 8][2] + ssum[wm][g + 8][3]);

    bf16* Pb = P + (size_t)b * Nn * Nn;
    const int row_lo = nblk * SB_M + wm * 16 + g;
    const int row_hi = row_lo + 8;
    #pragma unroll
    for (int j = 0; j < 32; ++j) {
        int col = wn * 256 + j * 8 + tc * 2;
        *(bf162*)&Pb[(size_t)row_lo * Nn + col] =
            __floats2bfloat162_rn(acc[j][0] * inv_lo, acc[j][1] * inv_lo);
        *(bf162*)&Pb[(size_t)row_hi * Nn + col] =
            __floats2bfloat162_rn(acc[j][2] * inv_hi, acc[j][3] * inv_hi);
    }
}

// ---------------- stage 1: weight convert ----------------
__global__ void wconv_kernel(const float* __restrict__ w1, const float* __restrict__ w2,
                             bf16* __restrict__ w1b, bf16* __restrict__ w2b) {
    int i = blockIdx.x * 256 + threadIdx.x;
    if (i < C3 * Cc) w1b[i] = __float2bfloat16(w1[i]);
    if (i < Cc * Cc) w2b[i] = __float2bfloat16(w2[i]);
}

// ---------------- stage 2: groupnorm stats ----------------
__global__ __launch_bounds__(256) void gn_stats_kernel(
        const float* __restrict__ x, const float* __restrict__ gns,
        const float* __restrict__ gnb, float* __restrict__ ga, float* __restrict__ gb) {
    int bg = blockIdx.x;
    const float4* p = reinterpret_cast<const float4*>(x) + (size_t)bg * 4096;
    float s = 0.f, ss = 0.f;
    for (int i = threadIdx.x; i < 4096; i += 256) {
        float4 v = p[i];
        s  += v.x + v.y + v.z + v.w;
        ss += v.x * v.x + v.y * v.y + v.z * v.z + v.w * v.w;
    }
    __shared__ float sh[34];
    #pragma unroll
    for (int o = 16; o > 0; o >>= 1) {
        s  += __shfl_xor_sync(~0u, s, o);
        ss += __shfl_xor_sync(~0u, ss, o);
    }
    int w = threadIdx.x >> 5;
    if ((threadIdx.x & 31) == 0) { sh[w] = s; sh[w + 8] = ss; }
    __syncthreads();
    if (threadIdx.x == 0) {
        float ts = 0.f, tss = 0.f;
        #pragma unroll
        for (int i = 0; i < 8; ++i) { ts += sh[i]; tss += sh[i + 8]; }
        sh[32] = ts; sh[33] = tss;
    }
    __syncthreads();
    float mean = sh[32] * (1.f / 16384.f);
    float var  = sh[33] * (1.f / 16384.f) - mean * mean;
    float rstd = rsqrtf(var + 1e-5f);
    if (threadIdx.x < 16) {
        int b = bg >> 5, gI = bg & 31, c = gI * 16 + threadIdx.x;
        float sc = gns[c] * rstd;
        ga[b * Cc + c] = sc;
        gb[b * Cc + c] = gnb[c] - mean * sc;
    }
}

// ---------------- stage 3: normalize + transpose -> xnT[b][n][c] ----------------
__global__ void gn_apply_t_kernel(const float* __restrict__ x, const float* __restrict__ ga,
                                  const float* __restrict__ gb, bf16* __restrict__ xnT) {
    __shared__ float t[32][33];
    int b = blockIdx.z;
    const float* xb = x + (size_t)b * Cc * Nn;
    int n0 = blockIdx.x * 32, c0 = blockIdx.y * 32;
    #pragma unroll
    for (int j = 0; j < 4; ++j) {
        int c = c0 + threadIdx.y + 8 * j;
        float v = xb[(size_t)c * Nn + n0 + threadIdx.x];
        t[threadIdx.y + 8 * j][threadIdx.x] = v * ga[b * Cc + c] + gb[b * Cc + c];
    }
    __syncthreads();
    bf16* ob = xnT + (size_t)b * Nn * Cc;
    #pragma unroll
    for (int j = 0; j < 4; ++j) {
        int n = n0 + threadIdx.y + 8 * j;
        ob[(size_t)n * Cc + c0 + threadIdx.x] =
            __float2bfloat16(t[threadIdx.x][threadIdx.y + 8 * j]);
    }
}

// ---------------- host launcher ----------------
extern "C" void kernel_launch(void* const* d_in, const int* in_sizes, int n_in,
                              void* d_out, int out_size) {
    (void)in_sizes; (void)n_in; (void)out_size;
    const float* x   = (const float*)d_in[0];
    const float* gns = (const float*)d_in[1];
    const float* gnb = (const float*)d_in[2];
    const float* w1  = (const float*)d_in[3];
    const float* b1  = (const float*)d_in[4];
    const float* w2  = (const float*)d_in[5];
    const float* b2  = (const float*)d_in[6];
    float* out = (float*)d_out;

    void *pga, *pgb, *pw1, *pw2, *pxn, *pqkv, *pP, *pattn;
    cudaGetSymbolAddress(&pga, g_ga);
    cudaGetSymbolAddress(&pgb, g_gb);
    cudaGetSymbolAddress(&pw1, g_w1b);
    cudaGetSymbolAddress(&pw2, g_w2b);
    cudaGetSymbolAddress(&pxn, g_xnT);
    cudaGetSymbolAddress(&pqkv, g_qkv);
    cudaGetSymbolAddress(&pP, g_P);
    cudaGetSymbolAddress(&pattn, g_attn);

    cudaFuncSetAttribute(gemm_bt<0>, cudaFuncAttributeMaxDynamicSharedMemorySize, GSMEM);
    cudaFuncSetAttribute(gemm_bt<2>, cudaFuncAttributeMaxDynamicSharedMemorySize, GSMEM);
    cudaFuncSetAttribute(gemm_bt<3>, cudaFuncAttributeMaxDynamicSharedMemorySize, GSMEM);
    cudaFuncSetAttribute(s_softmax_kernel,
                         cudaFuncAttributeMaxDynamicSharedMemorySize, S_SMEM);

    // 1) weights -> bf16
    wconv_kernel<<<3072, 256>>>(w1, w2, (bf16*)pw1, (bf16*)pw2);
    // 2) groupnorm stats
    gn_stats_kernel<<<Bb * 32, 256>>>(x, gns, gnb, (float*)pga, (float*)pgb);
    // 3) normalize + transpose -> xnT [b,n,c]
    gn_apply_t_kernel<<<dim3(32, 16, Bb), dim3(32, 8)>>>(x, (float*)pga, (float*)pgb,
                                                         (bf16*)pxn);
    // 4) QKV: qkv[o,n] = w1[o,:] . xnT[n,:] + b1[o]
    gemm_bt<0><<<dim3(8, 12, Bb), 256, GSMEM>>>(
        (const bf16*)pw1, (const bf16*)pxn, pqkv, b1, nullptr,
        C3, Nn, Cc, Cc, Cc, Nn, 0L, (long)Nn * Cc, (long)C3 * Nn, 0L);
    // 5) fused S + softmax -> P bf16 (reads q,k straight from qkv)
    s_softmax_kernel<<<dim3(Nn / SB_M, Bb), 256, S_SMEM>>>((const bf16*)pqkv, (bf16*)pP);
    // 6) attn[n,c] = P[n,:] . v[c,:]   (v rows of qkv, [c,m] K-major)
    gemm_bt<2><<<dim3(4, 8, Bb), 256, GSMEM>>>(
        (const bf16*)pP, (const bf16*)pqkv + (size_t)2 * Cc * Nn, pattn, nullptr, nullptr,
        Nn, Cc, Nn, Nn, Nn, Cc, (long)Nn * Nn, (long)C3 * Nn, (long)Nn * Cc, 0L);
    // 7) out[o,n] = w2[o,:] . attn[n,:] + b2[o] + x[o,n]  (fused residual)
    gemm_bt<3><<<dim3(8, 4, Bb), 256, GSMEM>>>(
        (const bf16*)pw2, (const bf16*)pattn, out, b2, x,
        Cc, Nn, Cc, Cc, Cc, Nn, 0L, (long)Nn * Cc, (long)Cc * Nn, (long)Cc * Nn);
}

// round 9
// speedup vs baseline: 1.2101x; 1.1340x over previous
#include <cuda_runtime.h>
#include <cuda_bf16.h>
#include <cstdint>

using bf16  = __nv_bfloat16;
using bf162 = __nv_bfloat162;

static constexpr int Bb = 32, Cc = 512, Nn = 1024, C3 = 1536;

// ---------------- device scratch ----------------
__device__ __align__(16) float g_ga[Bb * Cc];
__device__ __align__(16) float g_gb[Bb * Cc];
__device__ __align__(16) bf16  g_w1b[C3 * Cc];
__device__ __align__(16) bf16  g_w2b[Cc * Cc];
__device__ __align__(16) bf16  g_xnT [(size_t)Bb * Nn * Cc];
__device__ __align__(16) bf16  g_qkv [(size_t)Bb * C3 * Nn];
__device__ __align__(16) bf16  g_E   [(size_t)Bb * Nn * Nn];
__device__ __align__(16) float g_psum[(size_t)Bb * Nn * 8];
__device__ __align__(16) bf16  g_attn[(size_t)Bb * Nn * Cc];

// ---------------- PTX helpers ----------------
__device__ __forceinline__ uint32_t smem_u32(const void* p) {
    return (uint32_t)__cvta_generic_to_shared(p);
}
__device__ __forceinline__ void cp_async16(uint32_t s, const void* g) {
    asm volatile("cp.async.cg.shared.global [%0], [%1], 16;\n" :: "r"(s), "l"(g));
}
__device__ __forceinline__ void cp_commit() {
    asm volatile("cp.async.commit_group;\n" ::: "memory");
}
template <int N>
__device__ __forceinline__ void cp_wait() {
    asm volatile("cp.async.wait_group %0;\n" :: "n"(N) : "memory");
}
__device__ __forceinline__ void ldsm_x4(uint32_t* r, uint32_t addr) {
    asm volatile("ldmatrix.sync.aligned.m8n8.x4.shared.b16 {%0,%1,%2,%3}, [%4];\n"
                 : "=r"(r[0]), "=r"(r[1]), "=r"(r[2]), "=r"(r[3]) : "r"(addr));
}
__device__ __forceinline__ void ldsm_x4_t(uint32_t* r, uint32_t addr) {
    asm volatile("ldmatrix.sync.aligned.m8n8.x4.trans.shared.b16 {%0,%1,%2,%3}, [%4];\n"
                 : "=r"(r[0]), "=r"(r[1]), "=r"(r[2]), "=r"(r[3]) : "r"(addr));
}
__device__ __forceinline__ void mma_16816(float* d, const uint32_t* a,
                                          uint32_t b0, uint32_t b1) {
    asm volatile("mma.sync.aligned.m16n8k16.row.col.f32.bf16.bf16.f32 "
                 "{%0,%1,%2,%3}, {%4,%5,%6,%7}, {%8,%9}, {%0,%1,%2,%3};\n"
                 : "+f"(d[0]), "+f"(d[1]), "+f"(d[2]), "+f"(d[3])
                 : "r"(a[0]), "r"(a[1]), "r"(a[2]), "r"(a[3]), "r"(b0), "r"(b1));
}

// ---------------- mma.sync GEMM: D[M,N] = A[M,K] @ B[N,K]^T (R4 config) -------
// 128x128 tile, 256 threads, 2x4 warps (warp 64x32), BK=64, 3 stages.
// EPI: 0 = bf16 + bias[row], 2 = bf16, 3 = f32 + bias[row] + resid,
//      5 = bf16 scaled by 1/rowsum (bias = psum[b][row][8] partials)
static constexpr int BM = 128, BN = 128, BK = 64, PAD = 8, NST = 3;
static constexpr int LDT = BK + PAD;
static constexpr int SAe = BM * LDT;
static constexpr int GSMEM = 2 * NST * SAe * 2;

template <int EPI>
__global__ __launch_bounds__(256) void gemm_bt(
        const bf16* __restrict__ A, const bf16* __restrict__ B, void* __restrict__ C,
        const float* __restrict__ bias, const float* __restrict__ resid,
        int M, int N, int K, int ldA, int ldB, int ldC,
        long sA, long sB, long sC, long sR) {
    extern __shared__ bf16 sm[];
    bf16* AsAll = sm;
    bf16* BsAll = sm + NST * SAe;

    const int tid = threadIdx.x, lane = tid & 31, wid = tid >> 5;
    const int wm = wid & 1, wn = wid >> 1;
    const int m0 = blockIdx.y * BM, n0 = blockIdx.x * BN, bz = blockIdx.z;
    A += (size_t)bz * sA;
    B += (size_t)bz * sB;

    float acc[4][4][4];
    #pragma unroll
    for (int i = 0; i < 4; ++i)
        #pragma unroll
        for (int j = 0; j < 4; ++j)
            #pragma unroll
            for (int k = 0; k < 4; ++k) acc[i][j][k] = 0.f;

    const int lr = tid >> 3, lc = (tid & 7) * 8;

    auto load_stage = [&](int kt, int s) {
        bf16* As = AsAll + s * SAe;
        bf16* Bs = BsAll + s * SAe;
        const bf16* Ag = A + (size_t)m0 * ldA + kt * BK;
        const bf16* Bg = B + (size_t)n0 * ldB + kt * BK;
        #pragma unroll
        for (int i = 0; i < 4; ++i) {
            int r = lr + i * 32;
            cp_async16(smem_u32(As + r * LDT + lc), Ag + (size_t)r * ldA + lc);
        }
        #pragma unroll
        for (int i = 0; i < 4; ++i) {
            int r = lr + i * 32;
            cp_async16(smem_u32(Bs + r * LDT + lc), Bg + (size_t)r * ldB + lc);
        }
        cp_commit();
    };

    const int KT = K / BK;
    load_stage(0, 0);
    load_stage(1, 1);

    int sIdx = 0;
    for (int kt = 0; kt < KT; ++kt) {
        if (kt == KT - 1) cp_wait<0>(); else cp_wait<1>();
        __syncthreads();
        if (kt + 2 < KT) {
            int ns = sIdx + 2; if (ns >= NST) ns -= NST;
            load_stage(kt + 2, ns);
        }

        const bf16* As = AsAll + sIdx * SAe;
        const bf16* Bs = BsAll + sIdx * SAe;
        uint32_t aAddr = smem_u32(As + (wm * 64 + (lane & 15)) * LDT + (lane >> 4) * 8);
        uint32_t bAddr = smem_u32(Bs + (wn * 32 + (lane & 15)) * LDT + (lane >> 4) * 8);

        #pragma unroll
        for (int ks = 0; ks < 4; ++ks) {
            uint32_t ar[4][4], br[2][4];
            #pragma unroll
            for (int mt = 0; mt < 4; ++mt)
                ldsm_x4(ar[mt], aAddr + (uint32_t)(mt * 16 * LDT + ks * 16) * 2);
            #pragma unroll
            for (int rg = 0; rg < 2; ++rg)
                ldsm_x4(br[rg], bAddr + (uint32_t)(rg * 16 * LDT + ks * 16) * 2);
            #pragma unroll
            for (int mt = 0; mt < 4; ++mt)
                #pragma unroll
                for (int nt = 0; nt < 4; ++nt)
                    mma_16816(acc[mt][nt], ar[mt],
                              br[nt >> 1][nt & 1], br[nt >> 1][(nt & 1) + 2]);
        }
        ++sIdx; if (sIdx >= NST) sIdx = 0;
    }

    const int g = lane >> 2, tc = lane & 3;
    #pragma unroll
    for (int mt = 0; mt < 4; ++mt) {
        int row = m0 + wm * 64 + mt * 16 + g;
        float bv0 = 0.f, bv1 = 0.f;
        if constexpr (EPI == 0 || EPI == 3) { bv0 = bias[row]; bv1 = bias[row + 8]; }
        float inv0 = 1.f, inv1 = 1.f;
        if constexpr (EPI == 5) {
            const float* p0 = bias + ((size_t)bz * Nn + row) * 8;
            const float* p1 = p0 + 64;  // (row + 8) * 8
            float s0 = 0.f, s1 = 0.f;
            #pragma unroll
            for (int t = 0; t < 8; ++t) { s0 += p0[t]; s1 += p1[t]; }
            inv0 = 1.f / s0;
            inv1 = 1.f / s1;
        }
        #pragma unroll
        for (int nt = 0; nt < 4; ++nt) {
            int col = n0 + wn * 32 + nt * 8 + tc * 2;
            float* a4 = acc[mt][nt];
            if constexpr (EPI == 3) {
                float* Cp = (float*)C + (size_t)bz * sC;
                float2 v0 = make_float2(a4[0], a4[1]);
                float2 v1 = make_float2(a4[2], a4[3]);
                const float* Rp = resid + (size_t)bz * sR;
                float2 x0 = *(const float2*)&Rp[(size_t)row * ldC + col];
                float2 x1 = *(const float2*)&Rp[(size_t)(row + 8) * ldC + col];
                v0.x += bv0 + x0.x; v0.y += bv0 + x0.y;
                v1.x += bv1 + x1.x; v1.y += bv1 + x1.y;
                *(float2*)&Cp[(size_t)row * ldC + col]       = v0;
                *(float2*)&Cp[(size_t)(row + 8) * ldC + col] = v1;
            } else if constexpr (EPI == 5) {
                bf16* Cp = (bf16*)C + (size_t)bz * sC;
                *(bf162*)&Cp[(size_t)row * ldC + col] =
                    __floats2bfloat162_rn(a4[0] * inv0, a4[1] * inv0);
                *(bf162*)&Cp[(size_t)(row + 8) * ldC + col] =
                    __floats2bfloat162_rn(a4[2] * inv1, a4[3] * inv1);
            } else {
                bf16* Cp = (bf16*)C + (size_t)bz * sC;
                *(bf162*)&Cp[(size_t)row * ldC + col] =
                    __floats2bfloat162_rn(a4[0] + bv0, a4[1] + bv0);
                *(bf162*)&Cp[(size_t)(row + 8) * ldC + col] =
                    __floats2bfloat162_rn(a4[2] + bv1, a4[3] + bv1);
            }
        }
    }
}

// ---------------- s_exp: E[n,m] = exp(scale * q.k), partial row sums ---------
// Both operands read from qkv [c][x] layout via trans-ldmatrix (maps validated
// in R8's fused kernel). 128x128 tile, BK=64, 2 stages, 256 thr (2x4 warps).
static constexpr int TLD  = 136;                    // 128 + 8 halves
static constexpr int TSZ  = 64 * TLD;               // elems per tile per stage
static constexpr int TSMEM = 2 * 2 * TSZ * 2;       // 69632 B

__global__ __launch_bounds__(256) void s_exp_kernel(
        const bf16* __restrict__ qkv, bf16* __restrict__ E, float* __restrict__ psum) {
    extern __shared__ bf16 tsm[];
    bf16* AsAll = tsm;
    bf16* BsAll = tsm + 2 * TSZ;
    __shared__ float rs[128][4];

    const int tid = threadIdx.x, lane = tid & 31, wid = tid >> 5;
    const int wm = wid & 1, wn = wid >> 1;
    const int m0 = blockIdx.y * 128, n0 = blockIdx.x * 128, bz = blockIdx.z;
    const bf16* qg = qkv + (size_t)bz * C3 * Nn;        // [c][n]
    const bf16* kg = qg + (size_t)Cc * Nn;              // [c][m]

    float acc[4][4][4];
    #pragma unroll
    for (int i = 0; i < 4; ++i)
        #pragma unroll
        for (int j = 0; j < 4; ++j)
            #pragma unroll
            for (int k = 0; k < 4; ++k) acc[i][j][k] = 0.f;

    const int lr = tid >> 4, lc = (tid & 15) * 8;   // 16 rows x 16 chunks

    auto load_stage = [&](int kt, int s) {
        bf16* As = AsAll + s * TSZ;
        bf16* Bs = BsAll + s * TSZ;
        #pragma unroll
        for (int i = 0; i < 4; ++i) {
            int r = lr + i * 16;   // c-row within tile
            cp_async16(smem_u32(As + r * TLD + lc),
                       qg + (size_t)(kt * 64 + r) * Nn + m0 + lc);
        }
        #pragma unroll
        for (int i = 0; i < 4; ++i) {
            int r = lr + i * 16;
            cp_async16(smem_u32(Bs + r * TLD + lc),
                       kg + (size_t)(kt * 64 + r) * Nn + n0 + lc);
        }
        cp_commit();
    };

    const int KT = Cc / 64;  // 8
    load_stage(0, 0);

    // trans-ldsm lane maps (validated in R8):
    const int aRow = (lane & 7) + ((lane & 16) >> 1);
    const int aOff = ((lane >> 3) & 1) * 8;
    const int bRow = lane & 15;
    const int bOff = (lane >> 4) * 8;

    for (int kt = 0; kt < KT; ++kt) {
        if (kt + 1 < KT) {
            load_stage(kt + 1, (kt + 1) & 1);
            cp_wait<1>();
        } else {
            cp_wait<0>();
        }
        __syncthreads();

        const bf16* As = AsAll + (kt & 1) * TSZ;
        const bf16* Bs = BsAll + (kt & 1) * TSZ;
        uint32_t aBase = smem_u32(As + aRow * TLD + wm * 64 + aOff);
        uint32_t bBase = smem_u32(Bs + bRow * TLD + wn * 32 + bOff);

        #pragma unroll
        for (int ks = 0; ks < 4; ++ks) {
            uint32_t ar[4][4], br[2][4];
            #pragma unroll
            for (int mt = 0; mt < 4; ++mt)
                ldsm_x4_t(ar[mt], aBase + (uint32_t)(ks * 16 * TLD + mt * 16) * 2);
            #pragma unroll
            for (int rg = 0; rg < 2; ++rg)
                ldsm_x4_t(br[rg], bBase + (uint32_t)(ks * 16 * TLD + rg * 16) * 2);
            #pragma unroll
            for (int mt = 0; mt < 4; ++mt)
                #pragma unroll
                for (int rg = 0; rg < 2; ++rg) {
                    mma_16816(acc[mt][rg * 2],     ar[mt], br[rg][0], br[rg][1]);
                    mma_16816(acc[mt][rg * 2 + 1], ar[mt], br[rg][2], br[rg][3]);
                }
        }
        __syncthreads();
    }

    // epilogue: exp, partial row sums (per col-tile), bf16 E
    const float scl = 0.04419417382415922f;  // 512^-0.5
    const int g = lane >> 2, tc = lane & 3;
    bf16* Eb = E + (size_t)bz * Nn * Nn;
    #pragma unroll
    for (int mt = 0; mt < 4; ++mt) {
        int rlocal = wm * 64 + mt * 16 + g;
        int row = m0 + rlocal;
        float rs_lo = 0.f, rs_hi = 0.f;
        #pragma unroll
        for (int nt = 0; nt < 4; ++nt) {
            float* a4 = acc[mt][nt];
            a4[0] = __expf(a4[0] * scl);
            a4[1] = __expf(a4[1] * scl);
            a4[2] = __expf(a4[2] * scl);
            a4[3] = __expf(a4[3] * scl);
            rs_lo += a4[0] + a4[1];
            rs_hi += a4[2] + a4[3];
            int col = n0 + wn * 32 + nt * 8 + tc * 2;
            *(bf162*)&Eb[(size_t)row * Nn + col] =
                __floats2bfloat162_rn(a4[0], a4[1]);
            *(bf162*)&Eb[(size_t)(row + 8) * Nn + col] =
                __floats2bfloat162_rn(a4[2], a4[3]);
        }
        rs_lo += __shfl_xor_sync(~0u, rs_lo, 1);
        rs_lo += __shfl_xor_sync(~0u, rs_lo, 2);
        rs_hi += __shfl_xor_sync(~0u, rs_hi, 1);
        rs_hi += __shfl_xor_sync(~0u, rs_hi, 2);
        if (tc == 0) {
            rs[rlocal][wn]     += 0.f;  // no-op to keep layout obvious
            rs[rlocal][wn]      = (mt == 0 && false) ? 0.f : rs_lo;  // set below properly
        }
        // NOTE: direct stores (no accumulation needed; each [rlocal][wn] written once)
        if (tc == 0) {
            rs[rlocal][wn]     = rs_lo;
            rs[rlocal + 8][wn] = rs_hi;
        }
    }
    __syncthreads();
    if (tid < 128) {
        float s = rs[tid][0] + rs[tid][1] + rs[tid][2] + rs[tid][3];
        psum[((size_t)bz * Nn + m0 + tid) * 8 + blockIdx.x] = s;
    }
}

// ---------------- stage 1: weight convert ----------------
__global__ void wconv_kernel(const float* __restrict__ w1, const float* __restrict__ w2,
                             bf16* __restrict__ w1b, bf16* __restrict__ w2b) {
    int i = blockIdx.x * 256 + threadIdx.x;
    if (i < C3 * Cc) w1b[i] = __float2bfloat16(w1[i]);
    if (i < Cc * Cc) w2b[i] = __float2bfloat16(w2[i]);
}

// ---------------- stage 2: groupnorm stats ----------------
__global__ __launch_bounds__(256) void gn_stats_kernel(
        const float* __restrict__ x, const float* __restrict__ gns,
        const float* __restrict__ gnb, float* __restrict__ ga, float* __restrict__ gb) {
    int bg = blockIdx.x;
    const float4* p = reinterpret_cast<const float4*>(x) + (size_t)bg * 4096;
    float s = 0.f, ss = 0.f;
    for (int i = threadIdx.x; i < 4096; i += 256) {
        float4 v = p[i];
        s  += v.x + v.y + v.z + v.w;
        ss += v.x * v.x + v.y * v.y + v.z * v.z + v.w * v.w;
    }
    __shared__ float sh[34];
    #pragma unroll
    for (int o = 16; o > 0; o >>= 1) {
        s  += __shfl_xor_sync(~0u, s, o);
        ss += __shfl_xor_sync(~0u, ss, o);
    }
    int w = threadIdx.x >> 5;
    if ((threadIdx.x & 31) == 0) { sh[w] = s; sh[w + 8] = ss; }
    __syncthreads();
    if (threadIdx.x == 0) {
        float ts = 0.f, tss = 0.f;
        #pragma unroll
        for (int i = 0; i < 8; ++i) { ts += sh[i]; tss += sh[i + 8]; }
        sh[32] = ts; sh[33] = tss;
    }
    __syncthreads();
    float mean = sh[32] * (1.f / 16384.f);
    float var  = sh[33] * (1.f / 16384.f) - mean * mean;
    float rstd = rsqrtf(var + 1e-5f);
    if (threadIdx.x < 16) {
        int b = bg >> 5, gI = bg & 31, c = gI * 16 + threadIdx.x;
        float sc = gns[c] * rstd;
        ga[b * Cc + c] = sc;
        gb[b * Cc + c] = gnb[c] - mean * sc;
    }
}

// ---------------- stage 3: normalize + transpose -> xnT[b][n][c] ----------------
__global__ void gn_apply_t_kernel(const float* __restrict__ x, const float* __restrict__ ga,
                                  const float* __restrict__ gb, bf16* __restrict__ xnT) {
    __shared__ float t[32][33];
    int b = blockIdx.z;
    const float* xb = x + (size_t)b * Cc * Nn;
    int n0 = blockIdx.x * 32, c0 = blockIdx.y * 32;
    #pragma unroll
    for (int j = 0; j < 4; ++j) {
        int c = c0 + threadIdx.y + 8 * j;
        float v = xb[(size_t)c * Nn + n0 + threadIdx.x];
        t[threadIdx.y + 8 * j][threadIdx.x] = v * ga[b * Cc + c] + gb[b * Cc + c];
    }
    __syncthreads();
    bf16* ob = xnT + (size_t)b * Nn * Cc;
    #pragma unroll
    for (int j = 0; j < 4; ++j) {
        int n = n0 + threadIdx.y + 8 * j;
        ob[(size_t)n * Cc + c0 + threadIdx.x] =
            __float2bfloat16(t[threadIdx.x][threadIdx.y + 8 * j]);
    }
}

// ---------------- host launcher ----------------
extern "C" void kernel_launch(void* const* d_in, const int* in_sizes, int n_in,
                              void* d_out, int out_size) {
    (void)in_sizes; (void)n_in; (void)out_size;
    const float* x   = (const float*)d_in[0];
    const float* gns = (const float*)d_in[1];
    const float* gnb = (const float*)d_in[2];
    const float* w1  = (const float*)d_in[3];
    const float* b1  = (const float*)d_in[4];
    const float* w2  = (const float*)d_in[5];
    const float* b2  = (const float*)d_in[6];
    float* out = (float*)d_out;

    void *pga, *pgb, *pw1, *pw2, *pxn, *pqkv, *pE, *pps, *pattn;
    cudaGetSymbolAddress(&pga, g_ga);
    cudaGetSymbolAddress(&pgb, g_gb);
    cudaGetSymbolAddress(&pw1, g_w1b);
    cudaGetSymbolAddress(&pw2, g_w2b);
    cudaGetSymbolAddress(&pxn, g_xnT);
    cudaGetSymbolAddress(&pqkv, g_qkv);
    cudaGetSymbolAddress(&pE, g_E);
    cudaGetSymbolAddress(&pps, g_psum);
    cudaGetSymbolAddress(&pattn, g_attn);

    cudaFuncSetAttribute(gemm_bt<0>, cudaFuncAttributeMaxDynamicSharedMemorySize, GSMEM);
    cudaFuncSetAttribute(gemm_bt<3>, cudaFuncAttributeMaxDynamicSharedMemorySize, GSMEM);
    cudaFuncSetAttribute(gemm_bt<5>, cudaFuncAttributeMaxDynamicSharedMemorySize, GSMEM);
    cudaFuncSetAttribute(s_exp_kernel, cudaFuncAttributeMaxDynamicSharedMemorySize, TSMEM);

    // 1) weights -> bf16
    wconv_kernel<<<3072, 256>>>(w1, w2, (bf16*)pw1, (bf16*)pw2);
    // 2) groupnorm stats
    gn_stats_kernel<<<Bb * 32, 256>>>(x, gns, gnb, (float*)pga, (float*)pgb);
    // 3) normalize + transpose -> xnT [b,n,c]
    gn_apply_t_kernel<<<dim3(32, 16, Bb), dim3(32, 8)>>>(x, (float*)pga, (float*)pgb,
                                                         (bf16*)pxn);
    // 4) QKV: qkv[o,n] = w1[o,:] . xnT[n,:] + b1[o]
    gemm_bt<0><<<dim3(8, 12, Bb), 256, GSMEM>>>(
        (const bf16*)pw1, (const bf16*)pxn, pqkv, b1, nullptr,
        C3, Nn, Cc, Cc, Cc, Nn, 0L, (long)Nn * Cc, (long)C3 * Nn, 0L);
    // 5) E = exp(scale * q^T k) + partial row sums (reads q,k straight from qkv)
    s_exp_kernel<<<dim3(8, 8, Bb), 256, TSMEM>>>((const bf16*)pqkv, (bf16*)pE,
                                                 (float*)pps);
    // 6) attn[n,c] = (1/rowsum[n]) * E[n,:] . v[c,:]
    gemm_bt<5><<<dim3(4, 8, Bb), 256, GSMEM>>>(
        (const bf16*)pE, (const bf16*)pqkv + (size_t)2 * Cc * Nn, pattn,
        (const float*)pps, nullptr,
        Nn, Cc, Nn, Nn, Nn, Cc, (long)Nn * Nn, (long)C3 * Nn, (long)Nn * Cc, 0L);
    // 7) out[o,n] = w2[o,:] . attn[n,:] + b2[o] + x[o,n]  (fused residual)
    gemm_bt<3><<<dim3(8, 4, Bb), 256, GSMEM>>>(
        (const bf16*)pw2, (const bf16*)pattn, out, b2, x,
        Cc, Nn, Cc, Cc, Cc, Nn, 0L, (long)Nn * Cc, (long)Cc * Nn, (long)Cc * Nn);
}